// round 14
// baseline (speedup 1.0000x reference)
#include <cuda_runtime.h>
#include <cuda_bf16.h>
#include <cuda_fp16.h>
#include <cstdint>
#include <math.h>

// Problem constants
#define BB   2
#define NN   4096
#define DIM  512
#define NH   8
#define DH   64
#define NT   (NN / 64)   // 64 key tiles
#define NX   (8192 * 512)
#define NW   (512 * 1536)

// Attention operands: single fp16, [B, H, N, DH]; Q pre-scaled by log2(e)/8.
#define QKV_ELEMS (BB * NH * NN * DH)
__device__ __align__(128) __half gQ[QKV_ELEMS];
__device__ __align__(128) __half gK[QKV_ELEMS];
__device__ __align__(128) __half gV[QKV_ELEMS];
// fp16 X and W for the single-term QKV GEMM
__device__ __align__(128) __half gXf[NX];
__device__ __align__(128) __half gWf[NW];

// ---------------------------------------------------------------------------
// helpers
// ---------------------------------------------------------------------------
__device__ __forceinline__ uint32_t smem_u32(const void* p) {
    uint32_t a;
    asm("{ .reg .u64 t; cvta.to.shared.u64 t, %1; cvt.u32.u64 %0, t; }"
        : "=r"(a) : "l"(p));
    return a;
}
__device__ __forceinline__ void mma_fp16(float* c, const uint32_t* a,
                                         uint32_t b0, uint32_t b1) {
    asm volatile(
        "mma.sync.aligned.m16n8k16.row.col.f32.f16.f16.f32 "
        "{%0,%1,%2,%3}, {%4,%5,%6,%7}, {%8,%9}, {%0,%1,%2,%3};"
        : "+f"(c[0]), "+f"(c[1]), "+f"(c[2]), "+f"(c[3])
        : "r"(a[0]), "r"(a[1]), "r"(a[2]), "r"(a[3]), "r"(b0), "r"(b1));
}
__device__ __forceinline__ void ldsm4(uint32_t* r, uint32_t a) {
    asm volatile("ldmatrix.sync.aligned.m8n8.x4.shared.b16 {%0,%1,%2,%3}, [%4];"
        : "=r"(r[0]), "=r"(r[1]), "=r"(r[2]), "=r"(r[3]) : "r"(a));
}
__device__ __forceinline__ void ldsm4t(uint32_t* r, uint32_t a) {
    asm volatile("ldmatrix.sync.aligned.m8n8.x4.trans.shared.b16 {%0,%1,%2,%3}, [%4];"
        : "=r"(r[0]), "=r"(r[1]), "=r"(r[2]), "=r"(r[3]) : "r"(a));
}
__device__ __forceinline__ void cp16(uint32_t s, const void* g) {
    asm volatile("cp.async.cg.shared.global [%0], [%1], 16;"
        :: "r"(s), "l"(__cvta_generic_to_global(g)) : "memory");
}
#define CP_COMMIT() asm volatile("cp.async.commit_group;" ::: "memory")
#define CP_WAIT1()  asm volatile("cp.async.wait_group 1;" ::: "memory")
#define CP_WAIT0()  asm volatile("cp.async.wait_group 0;" ::: "memory")

// Pack (x,y) into one f16x2 word (low half = x)
__device__ __forceinline__ uint32_t packf16(float x, float y) {
    uint32_t r;
    asm("cvt.rn.f16x2.f32 %0, %1, %2;" : "=r"(r) : "f"(y), "f"(x));
    return r;
}
// Fast 2^x
__device__ __forceinline__ float ex2(float x) {
    float y;
    asm("ex2.approx.ftz.f32 %0, %1;" : "=f"(y) : "f"(x));
    return y;
}

// ---------------------------------------------------------------------------
// Convert pre-pass: X and W fp32 -> single fp16 (2 float4 per thread for ILP)
// ---------------------------------------------------------------------------
__global__ __launch_bounds__(256) void conv_xw_kernel(
    const float* __restrict__ X, const float* __restrict__ W)
{
    const int nx4 = NX / 4;
    const int tot = nx4 + NW / 4;
    const int base = blockIdx.x * 512 + threadIdx.x;
    #pragma unroll
    for (int p = 0; p < 2; p++) {
        const int i = base + p * 256;
        if (i >= tot) continue;
        const float4* src;
        __half* dst;
        int o;
        if (i < nx4) { src = (const float4*)X; dst = gXf; o = i; }
        else         { src = (const float4*)W; dst = gWf; o = i - nx4; }
        float4 v = src[o];
        ((uint2*)dst)[o] = make_uint2(packf16(v.x, v.y), packf16(v.z, v.w));
    }
}

// ---------------------------------------------------------------------------
// QKV GEMM via mma.sync fp16 single-term: C[8192,1536] = X@W + b.
// CTA tile 64(M) x 128(N), 4 warps, k64 stages double-buffered.
// ---------------------------------------------------------------------------
#define ASTR 144
#define ATILE (64 * ASTR)           // 9216
#define BSTR 272
#define BTILE (64 * BSTR)           // 17408
#define QSTAGE (ATILE + BTILE)      // 26624
#define QSMEM  (2 * QSTAGE)         // 53248

#define QSCALE 0.1803368801111243f  // 0.125 * log2(e)

__global__ void __launch_bounds__(128) qkv_mma_kernel(const float* __restrict__ bias)
{
    extern __shared__ char sm[];
    const uint32_t sb = smem_u32(sm);
    const int tid  = threadIdx.x;
    const int wid  = tid >> 5;
    const int lane = tid & 31;
    const int n0   = blockIdx.x * 128;
    const int m0   = blockIdx.y * 64;

    auto issue = [&](int stage, int k0) {
        const uint32_t st = sb + stage * QSTAGE;
        #pragma unroll
        for (int i = 0; i < 4; i++) {
            const int idx = i * 128 + tid;
            const int row = idx >> 3;
            const int c   = idx & 7;
            cp16(st + row * ASTR + c * 16,
                 (const char*)gXf + ((size_t)(m0 + row) * 512 + k0) * 2 + c * 16);
        }
        #pragma unroll
        for (int i = 0; i < 8; i++) {
            const int idx = i * 128 + tid;
            const int row = idx >> 4;
            const int c   = idx & 15;
            cp16(st + ATILE + row * BSTR + c * 16,
                 (const char*)gWf + ((size_t)(k0 + row) * 1536 + n0) * 2 + c * 16);
        }
        CP_COMMIT();
    };

    float acc[16][4];
    #pragma unroll
    for (int n = 0; n < 16; n++)
        #pragma unroll
        for (int i = 0; i < 4; i++) acc[n][i] = 0.f;

    const int rowA = 16 * wid + (lane & 15);
    const int colA = (lane >> 4) * 16;
    const int browb = (lane & 7) + ((lane >> 3) & 1) * 8;
    const int bnhalf = lane >> 4;

    issue(0, 0);

    #pragma unroll 1
    for (int s = 0; s < 8; s++) {
        CP_WAIT0();
        __syncthreads();
        if (s + 1 < 8) issue((s + 1) & 1, (s + 1) * 64);
        const uint32_t ab = sb + (s & 1) * QSTAGE;
        const uint32_t bb = ab + ATILE;

        #pragma unroll
        for (int ks = 0; ks < 4; ks++) {
            uint32_t a[4];
            ldsm4(a, ab + rowA * ASTR + ks * 32 + colA);
            #pragma unroll
            for (int g = 0; g < 2; g++) {
                uint32_t bf[4][4];
                #pragma unroll
                for (int nt = 0; nt < 4; nt++) {
                    const uint32_t ad = bb + (ks * 16 + browb) * BSTR +
                                        (2 * (4 * g + nt) + bnhalf) * 16;
                    ldsm4t(bf[nt], ad);
                }
                #pragma unroll
                for (int nt = 0; nt < 4; nt++) {
                    const int n = 2 * (4 * g + nt);
                    mma_fp16(acc[n],     a, bf[nt][0], bf[nt][1]);
                    mma_fp16(acc[n + 1], a, bf[nt][2], bf[nt][3]);
                }
            }
        }
        __syncthreads();
    }

    // ---- epilogue: bias, prescale q, pack fp16, scatter ----
    // part/dst/scale are CTA-uniform: 128-col block never straddles a 512 boundary
    const int r  = lane >> 2;
    const int c2 = 2 * (lane & 3);
    const int part   = n0 >> 9;              // 0=q, 1=v, 2=k
    const int inner0 = (n0 & 511) + c2;
    const float sc   = (part == 0) ? QSCALE : 1.0f;
    __half* const dst = (part == 0) ? gQ : ((part == 1) ? gV : gK);
    #pragma unroll
    for (int nt8 = 0; nt8 < 16; nt8++) {
        const float2 bz = *(const float2*)(bias + n0 + 8 * nt8 + c2);
        const int inner = inner0 + 8 * nt8;
        const int head  = inner >> 6;
        const int dd    = inner & 63;
        #pragma unroll
        for (int half = 0; half < 2; half++) {
            const int m  = m0 + 16 * wid + r + 8 * half;
            const int b_ = m >> 12;
            const int n_ = m & 4095;
            const float v0 = (acc[nt8][2 * half + 0] + bz.x) * sc;
            const float v1 = (acc[nt8][2 * half + 1] + bz.y) * sc;
            const size_t idx = (((size_t)(b_ * NH + head)) * NN + n_) * DH + dd;
            *(uint32_t*)(dst + idx) = packf16(v0, v1);
        }
    }
}

// ===========================================================================
// Flash attention, fp16 single-term MMAs, bias-free softmax (P = 2^s raw;
// the normalizer cancels in O/l), row-sum l via ones-column MMA,
// FA2-style S(kt+1) overlap, 3-stage cp.async ring, 4 CTAs/SM.
// ===========================================================================

#define TSTRIDE 144
#define TILE_B  (64 * TSTRIDE)     // 9216
#define STAGE_B (2 * TILE_B)       // 18432: K, V
#define ATTN_SMEM (3 * STAGE_B)    // 55296

__global__ void __launch_bounds__(128, 4) attn_mma_kernel(float* __restrict__ out)
{
    extern __shared__ char sm[];
    const uint32_t sb = smem_u32(sm);
    const int tid  = threadIdx.x;
    const int wid  = tid >> 5;
    const int lane = tid & 31;
    const int q0   = blockIdx.x * 64;
    const int bh   = blockIdx.y;
    const int b_   = bh >> 3;
    const int h_   = bh & 7;

    const size_t bhoff = (size_t)bh * NN * DH;

    // ---- Q A-frags directly from fp16 global ----
    uint32_t qa[4][4];
    {
        const int r  = lane >> 2;
        const int c2 = 2 * (lane & 3);
        const __half* qp = gQ + bhoff + (size_t)(q0 + 16 * wid) * DH;
        #pragma unroll
        for (int ks = 0; ks < 4; ks++) {
            const int cb = 16 * ks + c2;
            qa[ks][0] = *(const uint32_t*)(qp + (size_t)r * DH + cb);
            qa[ks][1] = *(const uint32_t*)(qp + (size_t)(r + 8) * DH + cb);
            qa[ks][2] = *(const uint32_t*)(qp + (size_t)r * DH + cb + 8);
            qa[ks][3] = *(const uint32_t*)(qp + (size_t)(r + 8) * DH + cb + 8);
        }
    }

    const char* srcs[2] = { (const char*)(gK + bhoff), (const char*)(gV + bhoff) };

    auto issue = [&](uint32_t st, int k0) {
        #pragma unroll
        for (int i = 0; i < 8; i++) {
            const int t   = i >> 2;            // 0 = K, 1 = V
            const int rem = (i & 3) * 128 + tid;
            const int row = rem >> 3;
            const int c   = rem & 7;
            cp16(st + t * TILE_B + row * TSTRIDE + c * 16,
                 srcs[t] + (size_t)(k0 + row) * 128 + c * 16);
        }
        CP_COMMIT();
    };

    float O_[8][4];
    #pragma unroll
    for (int n = 0; n < 8; n++)
        #pragma unroll
        for (int i = 0; i < 4; i++) O_[n][i] = 0.f;
    float lacc[4] = {0.f, 0.f, 0.f, 0.f};    // l = P @ ones (extra n8 tile)

    // Constant B-fragment for the ones column (n==0 holds 1.0h pairs)
    const uint32_t bones = (lane < 4) ? 0x3C003C00u : 0u;

    const int krow_base = (lane & 7);
    const int khalf     = (lane >> 3) & 1;
    const int nhalf     = (lane >> 4);

    // S = Q K^T (single-term fp16); S in log2 domain (Q pre-scaled)
    auto computeS = [&](float (&s)[8][4], uint32_t kb) {
        #pragma unroll
        for (int n = 0; n < 8; n++)
            #pragma unroll
            for (int i = 0; i < 4; i++) s[n][i] = 0.f;
        #pragma unroll
        for (int ks = 0; ks < 4; ks++) {
            uint32_t kh[4][4];
            #pragma unroll
            for (int np = 0; np < 4; np++) {
                const int nrow = 8 * (2 * np + nhalf) + krow_base;
                ldsm4(kh[np], kb + nrow * TSTRIDE + ks * 32 + khalf * 16);
            }
            #pragma unroll
            for (int np = 0; np < 4; np++) {
                mma_fp16(s[2 * np],     qa[ks], kh[np][0], kh[np][1]);
                mma_fp16(s[2 * np + 1], qa[ks], kh[np][2], kh[np][3]);
            }
        }
    };

    // P = 2^s; O += P V; l += P @ ones  (single-term fp16)
    auto doPV = [&](float (&s)[8][4], uint32_t vb) {
        #pragma unroll
        for (int kk = 0; kk < 4; kk++) {
            uint32_t p[4];
            p[0] = packf16(ex2(s[2 * kk][0]),     ex2(s[2 * kk][1]));
            p[1] = packf16(ex2(s[2 * kk][2]),     ex2(s[2 * kk][3]));
            p[2] = packf16(ex2(s[2 * kk + 1][0]), ex2(s[2 * kk + 1][1]));
            p[3] = packf16(ex2(s[2 * kk + 1][2]), ex2(s[2 * kk + 1][3]));
            uint32_t vh[4][4];
            const int vrow = 16 * kk + krow_base + khalf * 8;
            #pragma unroll
            for (int np = 0; np < 4; np++)
                ldsm4t(vh[np], vb + vrow * TSTRIDE + (2 * np + nhalf) * 16);
            #pragma unroll
            for (int np = 0; np < 4; np++) {
                mma_fp16(O_[2 * np],     p, vh[np][0], vh[np][1]);
                mma_fp16(O_[2 * np + 1], p, vh[np][2], vh[np][3]);
            }
            mma_fp16(lacc, p, bones, bones);
        }
    };

    // 3-stage ring: bV = stage(kt), bK = stage(kt+1), bL = load target (kt+2)
    uint32_t bV = sb, bK = sb + STAGE_B, bL = sb + 2 * STAGE_B;
    issue(bV, 0);
    issue(bK, 64);
    CP_WAIT1();             // tile 0 landed
    __syncthreads();

    float sA[8][4], sB[8][4];
    computeS(sA, bV);       // S(0)

    #pragma unroll 1
    for (int kt = 0; kt < NT; kt += 2) {
        // ---- body kt (even): sA current, sB next ----
        CP_WAIT0();
        __syncthreads();
        if (kt + 2 < NT) issue(bL, (kt + 2) * 64);
        computeS(sB, bK);                  // S(kt+1)
        doPV(sA, bV + TILE_B);
        { uint32_t t = bV; bV = bK; bK = bL; bL = t; }

        // ---- body kt+1 (odd): sB current, sA next ----
        CP_WAIT0();
        __syncthreads();
        if (kt + 3 < NT) issue(bL, (kt + 3) * 64);
        if (kt + 2 < NT) computeS(sA, bK); // S(kt+2)
        doPV(sB, bV + TILE_B);
        { uint32_t t = bV; bV = bK; bK = bL; bL = t; }
    }

    // ---- epilogue: fetch l (col 0 of the ones-tile, lanes with lane&3==0) ----
    const float l0 = __shfl_sync(0xffffffffu, lacc[0], lane & 28);
    const float l1 = __shfl_sync(0xffffffffu, lacc[2], lane & 28);
    const float inv0 = 1.0f / l0;
    const float inv1 = 1.0f / l1;
    const int r  = lane >> 2;
    const int c2 = 2 * (lane & 3);
    const int qrow0 = q0 + 16 * wid + r;
    const int qrow1 = qrow0 + 8;
    float* o0 = out + ((size_t)(b_ * NN + qrow0)) * DIM + h_ * DH + c2;
    float* o1 = out + ((size_t)(b_ * NN + qrow1)) * DIM + h_ * DH + c2;
    #pragma unroll
    for (int n = 0; n < 8; n++) {
        *(float2*)(o0 + 8 * n) = make_float2(O_[n][0] * inv0, O_[n][1] * inv0);
        *(float2*)(o1 + 8 * n) = make_float2(O_[n][2] * inv1, O_[n][3] * inv1);
    }
}

extern "C" void kernel_launch(void* const* d_in, const int* in_sizes, int n_in,
                              void* d_out, int out_size)
{
    const float* x    = (const float*)d_in[0];   // [2,4096,512]
    const float* Wm   = (const float*)d_in[1];   // [512,1536]
    const float* bias = (const float*)d_in[2];   // [1536]
    float* out = (float*)d_out;                  // [2,4096,512]

    (void)in_sizes; (void)n_in; (void)out_size;

    const int tot4 = (NX + NW) / 4;
    conv_xw_kernel<<<(tot4 + 511) / 512, 256>>>(x, Wm);

    cudaFuncSetAttribute(qkv_mma_kernel, cudaFuncAttributeMaxDynamicSharedMemorySize,
                         QSMEM);
    dim3 g1(1536 / 128, 8192 / 64);              // 12 x 128
    qkv_mma_kernel<<<g1, 128, QSMEM>>>(bias);

    cudaFuncSetAttribute(attn_mma_kernel, cudaFuncAttributeMaxDynamicSharedMemorySize,
                         ATTN_SMEM);
    dim3 g2(NN / 64, BB * NH);                   // 64 x 16 = 1024 CTAs
    attn_mma_kernel<<<g2, 128, ATTN_SMEM>>>(out);
}

// round 15
// speedup vs baseline: 1.0779x; 1.0779x over previous
#include <cuda_runtime.h>
#include <cuda_bf16.h>
#include <cuda_fp16.h>
#include <cstdint>
#include <math.h>

// Problem constants
#define BB   2
#define NN   4096
#define DIM  512
#define NH   8
#define DH   64
#define NT   (NN / 64)   // 64 key tiles
#define NX   (8192 * 512)
#define NW   (512 * 1536)

// Attention operands: single fp16, [B, H, N, DH]; Q pre-scaled by log2(e)/8.
#define QKV_ELEMS (BB * NH * NN * DH)
__device__ __align__(128) __half gQ[QKV_ELEMS];
__device__ __align__(128) __half gK[QKV_ELEMS];
__device__ __align__(128) __half gV[QKV_ELEMS];
// fp16 X and W for the single-term QKV GEMM
__device__ __align__(128) __half gXf[NX];
__device__ __align__(128) __half gWf[NW];

// ---------------------------------------------------------------------------
// helpers
// ---------------------------------------------------------------------------
__device__ __forceinline__ uint32_t smem_u32(const void* p) {
    uint32_t a;
    asm("{ .reg .u64 t; cvta.to.shared.u64 t, %1; cvt.u32.u64 %0, t; }"
        : "=r"(a) : "l"(p));
    return a;
}
__device__ __forceinline__ void mma_fp16(float* c, const uint32_t* a,
                                         uint32_t b0, uint32_t b1) {
    asm volatile(
        "mma.sync.aligned.m16n8k16.row.col.f32.f16.f16.f32 "
        "{%0,%1,%2,%3}, {%4,%5,%6,%7}, {%8,%9}, {%0,%1,%2,%3};"
        : "+f"(c[0]), "+f"(c[1]), "+f"(c[2]), "+f"(c[3])
        : "r"(a[0]), "r"(a[1]), "r"(a[2]), "r"(a[3]), "r"(b0), "r"(b1));
}
__device__ __forceinline__ void ldsm4(uint32_t* r, uint32_t a) {
    asm volatile("ldmatrix.sync.aligned.m8n8.x4.shared.b16 {%0,%1,%2,%3}, [%4];"
        : "=r"(r[0]), "=r"(r[1]), "=r"(r[2]), "=r"(r[3]) : "r"(a));
}
__device__ __forceinline__ void ldsm4t(uint32_t* r, uint32_t a) {
    asm volatile("ldmatrix.sync.aligned.m8n8.x4.trans.shared.b16 {%0,%1,%2,%3}, [%4];"
        : "=r"(r[0]), "=r"(r[1]), "=r"(r[2]), "=r"(r[3]) : "r"(a));
}
__device__ __forceinline__ void cp16(uint32_t s, const void* g) {
    asm volatile("cp.async.cg.shared.global [%0], [%1], 16;"
        :: "r"(s), "l"(__cvta_generic_to_global(g)) : "memory");
}
#define CP_COMMIT() asm volatile("cp.async.commit_group;" ::: "memory")
#define CP_WAIT1()  asm volatile("cp.async.wait_group 1;" ::: "memory")
#define CP_WAIT0()  asm volatile("cp.async.wait_group 0;" ::: "memory")

// Pack (x,y) into one f16x2 word (low half = x)
__device__ __forceinline__ uint32_t packf16(float x, float y) {
    uint32_t r;
    asm("cvt.rn.f16x2.f32 %0, %1, %2;" : "=r"(r) : "f"(y), "f"(x));
    return r;
}
// Fast 2^x
__device__ __forceinline__ float ex2(float x) {
    float y;
    asm("ex2.approx.ftz.f32 %0, %1;" : "=f"(y) : "f"(x));
    return y;
}

// ---------------------------------------------------------------------------
// Convert pre-pass: X and W fp32 -> single fp16 (2 float4 per thread for ILP)
// ---------------------------------------------------------------------------
__global__ __launch_bounds__(256) void conv_xw_kernel(
    const float* __restrict__ X, const float* __restrict__ W)
{
    const int nx4 = NX / 4;
    const int tot = nx4 + NW / 4;
    const int base = blockIdx.x * 512 + threadIdx.x;
    #pragma unroll
    for (int p = 0; p < 2; p++) {
        const int i = base + p * 256;
        if (i >= tot) continue;
        const float4* src;
        __half* dst;
        int o;
        if (i < nx4) { src = (const float4*)X; dst = gXf; o = i; }
        else         { src = (const float4*)W; dst = gWf; o = i - nx4; }
        float4 v = src[o];
        ((uint2*)dst)[o] = make_uint2(packf16(v.x, v.y), packf16(v.z, v.w));
    }
}

// ---------------------------------------------------------------------------
// QKV GEMM via mma.sync fp16 single-term: C[8192,1536] = X@W + b.
// CTA tile 64(M) x 128(N), 4 warps, k64 stages double-buffered.
// ---------------------------------------------------------------------------
#define ASTR 144
#define ATILE (64 * ASTR)           // 9216
#define BSTR 272
#define BTILE (64 * BSTR)           // 17408
#define QSTAGE (ATILE + BTILE)      // 26624
#define QSMEM  (2 * QSTAGE)         // 53248

#define QSCALE 0.1803368801111243f  // 0.125 * log2(e)

__global__ void __launch_bounds__(128) qkv_mma_kernel(const float* __restrict__ bias)
{
    extern __shared__ char sm[];
    const uint32_t sb = smem_u32(sm);
    const int tid  = threadIdx.x;
    const int wid  = tid >> 5;
    const int lane = tid & 31;
    const int n0   = blockIdx.x * 128;
    const int m0   = blockIdx.y * 64;

    auto issue = [&](int stage, int k0) {
        const uint32_t st = sb + stage * QSTAGE;
        #pragma unroll
        for (int i = 0; i < 4; i++) {
            const int idx = i * 128 + tid;
            const int row = idx >> 3;
            const int c   = idx & 7;
            cp16(st + row * ASTR + c * 16,
                 (const char*)gXf + ((size_t)(m0 + row) * 512 + k0) * 2 + c * 16);
        }
        #pragma unroll
        for (int i = 0; i < 8; i++) {
            const int idx = i * 128 + tid;
            const int row = idx >> 4;
            const int c   = idx & 15;
            cp16(st + ATILE + row * BSTR + c * 16,
                 (const char*)gWf + ((size_t)(k0 + row) * 1536 + n0) * 2 + c * 16);
        }
        CP_COMMIT();
    };

    float acc[16][4];
    #pragma unroll
    for (int n = 0; n < 16; n++)
        #pragma unroll
        for (int i = 0; i < 4; i++) acc[n][i] = 0.f;

    const int rowA = 16 * wid + (lane & 15);
    const int colA = (lane >> 4) * 16;
    const int browb = (lane & 7) + ((lane >> 3) & 1) * 8;
    const int bnhalf = lane >> 4;

    issue(0, 0);

    #pragma unroll 1
    for (int s = 0; s < 8; s++) {
        CP_WAIT0();
        __syncthreads();
        if (s + 1 < 8) issue((s + 1) & 1, (s + 1) * 64);
        const uint32_t ab = sb + (s & 1) * QSTAGE;
        const uint32_t bb = ab + ATILE;

        #pragma unroll
        for (int ks = 0; ks < 4; ks++) {
            uint32_t a[4];
            ldsm4(a, ab + rowA * ASTR + ks * 32 + colA);
            #pragma unroll
            for (int g = 0; g < 2; g++) {
                uint32_t bf[4][4];
                #pragma unroll
                for (int nt = 0; nt < 4; nt++) {
                    const uint32_t ad = bb + (ks * 16 + browb) * BSTR +
                                        (2 * (4 * g + nt) + bnhalf) * 16;
                    ldsm4t(bf[nt], ad);
                }
                #pragma unroll
                for (int nt = 0; nt < 4; nt++) {
                    const int n = 2 * (4 * g + nt);
                    mma_fp16(acc[n],     a, bf[nt][0], bf[nt][1]);
                    mma_fp16(acc[n + 1], a, bf[nt][2], bf[nt][3]);
                }
            }
        }
        __syncthreads();
    }

    // ---- epilogue: bias, prescale q, pack fp16, scatter ----
    const int r  = lane >> 2;
    const int c2 = 2 * (lane & 3);
    const int part   = n0 >> 9;              // 0=q, 1=v, 2=k
    const int inner0 = (n0 & 511) + c2;
    const float sc   = (part == 0) ? QSCALE : 1.0f;
    __half* const dst = (part == 0) ? gQ : ((part == 1) ? gV : gK);
    #pragma unroll
    for (int nt8 = 0; nt8 < 16; nt8++) {
        const float2 bz = *(const float2*)(bias + n0 + 8 * nt8 + c2);
        const int inner = inner0 + 8 * nt8;
        const int head  = inner >> 6;
        const int dd    = inner & 63;
        #pragma unroll
        for (int half = 0; half < 2; half++) {
            const int m  = m0 + 16 * wid + r + 8 * half;
            const int b_ = m >> 12;
            const int n_ = m & 4095;
            const float v0 = (acc[nt8][2 * half + 0] + bz.x) * sc;
            const float v1 = (acc[nt8][2 * half + 1] + bz.y) * sc;
            const size_t idx = (((size_t)(b_ * NH + head)) * NN + n_) * DH + dd;
            *(uint32_t*)(dst + idx) = packf16(v0, v1);
        }
    }
}

// ===========================================================================
// Flash attention, fp16 single-term MMAs, bias-free softmax (P = 2^s raw),
// row-sum l via ones-column MMA, SINGLE S buffer (low regs) + 4 CTAs/SM for
// cross-CTA latency hiding, 3-stage cp.async ring.
// ===========================================================================

#define TSTRIDE 144
#define TILE_B  (64 * TSTRIDE)     // 9216
#define STAGE_B (2 * TILE_B)       // 18432: K, V
#define ATTN_SMEM (3 * STAGE_B)    // 55296; x4 CTAs = 221184 <= 228KB

__global__ void __launch_bounds__(128, 4) attn_mma_kernel(float* __restrict__ out)
{
    extern __shared__ char sm[];
    const uint32_t sb = smem_u32(sm);
    const int tid  = threadIdx.x;
    const int wid  = tid >> 5;
    const int lane = tid & 31;
    const int q0   = blockIdx.x * 64;
    const int bh   = blockIdx.y;
    const int b_   = bh >> 3;
    const int h_   = bh & 7;

    const size_t bhoff = (size_t)bh * NN * DH;

    // ---- Q A-frags directly from fp16 global ----
    uint32_t qa[4][4];
    {
        const int r  = lane >> 2;
        const int c2 = 2 * (lane & 3);
        const __half* qp = gQ + bhoff + (size_t)(q0 + 16 * wid) * DH;
        #pragma unroll
        for (int ks = 0; ks < 4; ks++) {
            const int cb = 16 * ks + c2;
            qa[ks][0] = *(const uint32_t*)(qp + (size_t)r * DH + cb);
            qa[ks][1] = *(const uint32_t*)(qp + (size_t)(r + 8) * DH + cb);
            qa[ks][2] = *(const uint32_t*)(qp + (size_t)r * DH + cb + 8);
            qa[ks][3] = *(const uint32_t*)(qp + (size_t)(r + 8) * DH + cb + 8);
        }
    }

    const char* srcs[2] = { (const char*)(gK + bhoff), (const char*)(gV + bhoff) };

    auto issue = [&](uint32_t st, int k0) {
        #pragma unroll
        for (int i = 0; i < 8; i++) {
            const int t   = i >> 2;            // 0 = K, 1 = V
            const int rem = (i & 3) * 128 + tid;
            const int row = rem >> 3;
            const int c   = rem & 7;
            cp16(st + t * TILE_B + row * TSTRIDE + c * 16,
                 srcs[t] + (size_t)(k0 + row) * 128 + c * 16);
        }
        CP_COMMIT();
    };

    float O_[8][4];
    #pragma unroll
    for (int n = 0; n < 8; n++)
        #pragma unroll
        for (int i = 0; i < 4; i++) O_[n][i] = 0.f;
    float lacc[4] = {0.f, 0.f, 0.f, 0.f};    // l = P @ ones (extra n8 tile)

    // Constant B-fragment for the ones column (n==0 holds 1.0h pairs)
    const uint32_t bones = (lane < 4) ? 0x3C003C00u : 0u;

    const int krow_base = (lane & 7);
    const int khalf     = (lane >> 3) & 1;
    const int nhalf     = (lane >> 4);

    // 3-stage ring, loads issued 2 tiles ahead
    uint32_t stg[3] = { sb, sb + STAGE_B, sb + 2 * STAGE_B };
    issue(stg[0], 0);
    issue(stg[1], 64);

    int cur = 0;
    #pragma unroll 1
    for (int kt = 0; kt < NT; kt++) {
        if (kt + 1 < NT) { CP_WAIT1(); } else { CP_WAIT0(); }
        __syncthreads();               // stage kt ready; prev body done with ring
        if (kt + 2 < NT) issue(stg[(cur + 2) % 3], (kt + 2) * 64);

        const uint32_t kb = stg[cur];
        const uint32_t vb = kb + TILE_B;

        // ---- S = Q K^T (single-term fp16, log2 domain) ----
        float s[8][4];
        #pragma unroll
        for (int n = 0; n < 8; n++)
            #pragma unroll
            for (int i = 0; i < 4; i++) s[n][i] = 0.f;
        #pragma unroll
        for (int ks = 0; ks < 4; ks++) {
            uint32_t kh[4][4];
            #pragma unroll
            for (int np = 0; np < 4; np++) {
                const int nrow = 8 * (2 * np + nhalf) + krow_base;
                ldsm4(kh[np], kb + nrow * TSTRIDE + ks * 32 + khalf * 16);
            }
            #pragma unroll
            for (int np = 0; np < 4; np++) {
                mma_fp16(s[2 * np],     qa[ks], kh[np][0], kh[np][1]);
                mma_fp16(s[2 * np + 1], qa[ks], kh[np][2], kh[np][3]);
            }
        }

        // ---- P = 2^s; O += P V; l += P @ ones ----
        #pragma unroll
        for (int kk = 0; kk < 4; kk++) {
            uint32_t p[4];
            p[0] = packf16(ex2(s[2 * kk][0]),     ex2(s[2 * kk][1]));
            p[1] = packf16(ex2(s[2 * kk][2]),     ex2(s[2 * kk][3]));
            p[2] = packf16(ex2(s[2 * kk + 1][0]), ex2(s[2 * kk + 1][1]));
            p[3] = packf16(ex2(s[2 * kk + 1][2]), ex2(s[2 * kk + 1][3]));
            uint32_t vh[4][4];
            const int vrow = 16 * kk + krow_base + khalf * 8;
            #pragma unroll
            for (int np = 0; np < 4; np++)
                ldsm4t(vh[np], vb + vrow * TSTRIDE + (2 * np + nhalf) * 16);
            #pragma unroll
            for (int np = 0; np < 4; np++) {
                mma_fp16(O_[2 * np],     p, vh[np][0], vh[np][1]);
                mma_fp16(O_[2 * np + 1], p, vh[np][2], vh[np][3]);
            }
            mma_fp16(lacc, p, bones, bones);
        }

        cur = (cur + 1) % 3;
    }

    // ---- epilogue: fetch l (col 0 of the ones-tile, lanes with lane&3==0) ----
    const float l0 = __shfl_sync(0xffffffffu, lacc[0], lane & 28);
    const float l1 = __shfl_sync(0xffffffffu, lacc[2], lane & 28);
    const float inv0 = 1.0f / l0;
    const float inv1 = 1.0f / l1;
    const int r  = lane >> 2;
    const int c2 = 2 * (lane & 3);
    const int qrow0 = q0 + 16 * wid + r;
    const int qrow1 = qrow0 + 8;
    float* o0 = out + ((size_t)(b_ * NN + qrow0)) * DIM + h_ * DH + c2;
    float* o1 = out + ((size_t)(b_ * NN + qrow1)) * DIM + h_ * DH + c2;
    #pragma unroll
    for (int n = 0; n < 8; n++) {
        *(float2*)(o0 + 8 * n) = make_float2(O_[n][0] * inv0, O_[n][1] * inv0);
        *(float2*)(o1 + 8 * n) = make_float2(O_[n][2] * inv1, O_[n][3] * inv1);
    }
}

extern "C" void kernel_launch(void* const* d_in, const int* in_sizes, int n_in,
                              void* d_out, int out_size)
{
    const float* x    = (const float*)d_in[0];   // [2,4096,512]
    const float* Wm   = (const float*)d_in[1];   // [512,1536]
    const float* bias = (const float*)d_in[2];   // [1536]
    float* out = (float*)d_out;                  // [2,4096,512]

    (void)in_sizes; (void)n_in; (void)out_size;

    const int tot4 = (NX + NW) / 4;
    conv_xw_kernel<<<(tot4 + 511) / 512, 256>>>(x, Wm);

    cudaFuncSetAttribute(qkv_mma_kernel, cudaFuncAttributeMaxDynamicSharedMemorySize,
                         QSMEM);
    dim3 g1(1536 / 128, 8192 / 64);              // 12 x 128
    qkv_mma_kernel<<<g1, 128, QSMEM>>>(bias);

    cudaFuncSetAttribute(attn_mma_kernel, cudaFuncAttributeMaxDynamicSharedMemorySize,
                         ATTN_SMEM);
    dim3 g2(NN / 64, BB * NH);                   // 64 x 16 = 1024 CTAs
    attn_mma_kernel<<<g2, 128, ATTN_SMEM>>>(out);
}